// round 14
// baseline (speedup 1.0000x reference)
#include <cuda_runtime.h>
#include <cuda_bf16.h>
#include <cstdint>

// Tree: DIM=3, FBITS=8, K=4, DEPTH=10. POS[t]=(4^t-1)/3.
// Identity (verified since R4, rel_err ~3e-8): with full 30-bit reversal,
//   X_rev = sum_t rev3(j_t) << 3t; c0=X&1023, c1=(X>>10)&1023, c2=X>>20.
//
// R12 (= R11 resubmit after infra failure): 1 thread = level-9 node
// (4 leaves). No shared memory, no barrier, no global LUT load.
// Byte -> packed rev3(set-bit-position) lookup via a warp-register LUT
// accessed with __shfl_sync:
//   lanes  0..15 : pack of low  nibble, fields = rev3(b)   in {0,4,2,6}
//   lanes 16..31 : pack of high nibble, fields = rev3(b+4) = rev3(b)|1
//   pack(f) = lo(f&15) | hi(f>>4) << 3*popc(f&15)

#define BLOCK   256
#define NBLOCKS 1024     // 262144 level-9 nodes

__device__ __forceinline__ unsigned lut_lookup(unsigned pk, unsigned f)
{
    unsigned lo = (unsigned)__shfl_sync(0xffffffffu, (int)pk, (int)(f & 15u));
    unsigned hi = (unsigned)__shfl_sync(0xffffffffu, (int)pk, (int)(16u + (f >> 4)));
    return lo | (hi << (3u * (unsigned)__popc(f & 15u)));
}

__global__ void __launch_bounds__(BLOCK)
nbit_decode_kernel(const int* __restrict__ flags,
                   const float* __restrict__ offset,
                   const float* __restrict__ scale,
                   float* __restrict__ out)
{
    const unsigned n9 = blockIdx.x * BLOCK + threadIdx.x;

    // ---- Issue ALL global loads first (overlap with LUT build) ----
    const unsigned fl0 = (unsigned)__ldg(&flags[0])                       & 255u;
    const unsigned fl1 = (unsigned)__ldg(&flags[1     + (int)(n9 >> 16)]) & 255u;
    const unsigned fl2 = (unsigned)__ldg(&flags[5     + (int)(n9 >> 14)]) & 255u;
    const unsigned fl3 = (unsigned)__ldg(&flags[21    + (int)(n9 >> 12)]) & 255u;
    const unsigned fl4 = (unsigned)__ldg(&flags[85    + (int)(n9 >> 10)]) & 255u;
    const unsigned fl5 = (unsigned)__ldg(&flags[341   + (int)(n9 >> 8)])  & 255u;
    const unsigned fl6 = (unsigned)__ldg(&flags[1365  + (int)(n9 >> 6)])  & 255u;
    const unsigned fl7 = (unsigned)__ldg(&flags[5461  + (int)(n9 >> 4)])  & 255u;
    const unsigned fl8 = (unsigned)__ldg(&flags[21845 + (int)(n9 >> 2)])  & 255u;
    const unsigned fl9 = (unsigned)__ldg(&flags[87381 + (int)n9])         & 255u;
    const float s0 = __ldg(&scale[0]),  s1 = __ldg(&scale[1]),  s2 = __ldg(&scale[2]);
    const float o0 = __ldg(&offset[0]), o1 = __ldg(&offset[1]), o2 = __ldg(&offset[2]);

    // ---- Build nibble LUT in registers ----
    // lane & 16 selects high-nibble variant: each field gets |1 (rev3(b+4)=rev3(b)|1)
    const unsigned lane = threadIdx.x & 31u;
    const unsigned nib  = lane & 15u;
    const unsigned add  = (lane >> 4) & 1u;
    unsigned pk = 0, rank = 0;
    if (nib & 1u) { pk |= (0u + add) << (3u * rank); ++rank; }
    if (nib & 2u) { pk |= (4u + add) << (3u * rank); ++rank; }
    if (nib & 4u) { pk |= (2u + add) << (3u * rank); ++rank; }
    if (nib & 8u) { pk |= (6u + add) << (3u * rank);         }

    // ---- Decode: OR-tree of per-level 3-bit contributions ----
    const unsigned a0 = ((lut_lookup(pk, fl0) >> (3u * ((n9 >> 16) & 3u))) & 7u);
    const unsigned a1 = ((lut_lookup(pk, fl1) >> (3u * ((n9 >> 14) & 3u))) & 7u) << 3;
    const unsigned a2 = ((lut_lookup(pk, fl2) >> (3u * ((n9 >> 12) & 3u))) & 7u) << 6;
    const unsigned a3 = ((lut_lookup(pk, fl3) >> (3u * ((n9 >> 10) & 3u))) & 7u) << 9;
    const unsigned a4 = ((lut_lookup(pk, fl4) >> (3u * ((n9 >>  8) & 3u))) & 7u) << 12;
    const unsigned a5 = ((lut_lookup(pk, fl5) >> (3u * ((n9 >>  6) & 3u))) & 7u) << 15;
    const unsigned a6 = ((lut_lookup(pk, fl6) >> (3u * ((n9 >>  4) & 3u))) & 7u) << 18;
    const unsigned a7 = ((lut_lookup(pk, fl7) >> (3u * ((n9 >>  2) & 3u))) & 7u) << 21;
    const unsigned a8 = ((lut_lookup(pk, fl8) >> (3u * ( n9        & 3u))) & 7u) << 24;
    const unsigned p9 = lut_lookup(pk, fl9);        // all 4 leaf contributions

    const unsigned acc = ((a0 | a1) | (a2 | a3)) | ((a4 | a5) | (a6 | a7)) | a8;

    // c0, c1 shared by the 4 leaves; c2 varies only in its top 3 bits.
    const float v0    = (float)(acc & 1023u)         * s0 + o0;
    const float v1    = (float)((acc >> 10) & 1023u) * s1 + o1;
    const float fbase = (float)((acc >> 20) & 127u)  * s2 + o2;
    const float s2h   = s2 * 128.0f;

    const float vc0 = (float)( p9        & 7u) * s2h + fbase;
    const float vc1 = (float)((p9 >> 3)  & 7u) * s2h + fbase;
    const float vc2 = (float)((p9 >> 6)  & 7u) * s2h + fbase;
    const float vc3 = (float)((p9 >> 9)  & 7u) * s2h + fbase;

    // 12 consecutive floats (48B, 16B-aligned): 3 streaming STG.128.
    float4* o4 = reinterpret_cast<float4*>(out + (size_t)n9 * 12u);
    __stcs(o4 + 0, make_float4(v0,  v1,  vc0, v0));
    __stcs(o4 + 1, make_float4(v1,  vc1, v0,  v1));
    __stcs(o4 + 2, make_float4(vc2, v0,  v1,  vc3));
}

extern "C" void kernel_launch(void* const* d_in, const int* in_sizes, int n_in,
                              void* d_out, int out_size)
{
    const int*   flags  = (const int*)  d_in[0];
    const float* offset = (const float*)d_in[1];
    const float* scale  = (const float*)d_in[2];
    if (n_in == 3 && in_sizes[0] == 3) {   // defensive input-order handling
        int fi = (in_sizes[1] > 3) ? 1 : 2;
        flags = (const int*)d_in[fi];
        int s1 = -1, s2 = -1;
        for (int i = 0; i < 3; ++i) {
            if (i == fi) continue;
            if (s1 < 0) s1 = i; else s2 = i;
        }
        offset = (const float*)d_in[s1];
        scale  = (const float*)d_in[s2];
    }

    nbit_decode_kernel<<<NBLOCKS, BLOCK>>>(flags, offset, scale, (float*)d_out);
}